// round 1
// baseline (speedup 1.0000x reference)
#include <cuda_runtime.h>
#include <math.h>

#define NB    16
#define C     384
#define C3    1152
#define HIN   64
#define HH    16
#define L     256          // HH*HH
#define HEADS 12
#define HD    32
#define EPS   1e-5f

// ---------------- scratch (device globals: allocation-free) ----------------
__device__ float g_xd  [NB * C  * L];   // x_down after conv+BN
__device__ float g_xd2 [NB * C  * L];   // after channel attention
__device__ float g_gn  [NB * C  * L];   // groupnorm output
__device__ float g_qkv [NB * C3 * L];   // qkv projections
__device__ float g_att [NB * C  * C];   // channel attention matrix
__device__ float g_vals[NB * C  * L];   // attention values
__device__ float g_stat[NB * 2];        // per-sample mean, inv_std

// ---------------- depthwise 7x7 stride-4 conv + folded BatchNorm -----------
__global__ void __launch_bounds__(256) k_dwconv(
    const float* __restrict__ x, const float* __restrict__ w,
    const float* __restrict__ bg, const float* __restrict__ bb,
    const float* __restrict__ bm, const float* __restrict__ bv)
{
    __shared__ float sx[HIN * HIN];   // 16 KB: full 64x64 channel plane
    __shared__ float sw[49];
    int n = blockIdx.x / C, c = blockIdx.x % C;
    const float* xp = x + ((size_t)n * C + c) * (HIN * HIN);
    for (int i = threadIdx.x; i < HIN * HIN; i += 256) sx[i] = xp[i];
    if (threadIdx.x < 49) sw[threadIdx.x] = w[c * 49 + threadIdx.x];
    __syncthreads();

    float scale = bg[c] * rsqrtf(bv[c] + EPS);
    float bias  = bb[c] - bm[c] * scale;

    int oy = threadIdx.x >> 4, ox = threadIdx.x & 15;
    int iy0 = oy * 4 - 3, ix0 = ox * 4 - 3;
    float acc = 0.f;
    #pragma unroll
    for (int ky = 0; ky < 7; ky++) {
        int iy = iy0 + ky;
        if ((unsigned)iy < (unsigned)HIN) {
            #pragma unroll
            for (int kx = 0; kx < 7; kx++) {
                int ix = ix0 + kx;
                if ((unsigned)ix < (unsigned)HIN)
                    acc += sx[iy * HIN + ix] * sw[ky * 7 + kx];
            }
        }
    }
    g_xd[((size_t)n * C + c) * L + threadIdx.x] = acc * scale + bias;
}

// ---------------- GroupNorm (1 group): per-sample stats --------------------
__device__ __forceinline__ float warpsum(float v) {
    #pragma unroll
    for (int o = 16; o; o >>= 1) v += __shfl_down_sync(0xffffffffu, v, o);
    return v;
}

__global__ void __launch_bounds__(1024) k_gnstats(const float* __restrict__ p0) {
    const float* p = p0 + (size_t)blockIdx.x * C * L;
    float s = 0.f, s2 = 0.f;
    for (int i = threadIdx.x; i < C * L; i += 1024) {
        float t = p[i]; s += t; s2 += t * t;
    }
    __shared__ float a[32], b[32];
    s = warpsum(s); s2 = warpsum(s2);
    int w = threadIdx.x >> 5, ln = threadIdx.x & 31;
    if (ln == 0) { a[w] = s; b[w] = s2; }
    __syncthreads();
    if (w == 0) {
        s = a[ln]; s2 = b[ln];
        s = warpsum(s); s2 = warpsum(s2);
        if (ln == 0) {
            float inv = 1.f / (C * L);
            float mean = s * inv;
            float var  = s2 * inv - mean * mean;
            g_stat[blockIdx.x * 2]     = mean;
            g_stat[blockIdx.x * 2 + 1] = rsqrtf(var + EPS);
        }
    }
}

__global__ void __launch_bounds__(256) k_gnapply(
    const float* __restrict__ in, float* __restrict__ out,
    const float* __restrict__ gamma, const float* __restrict__ beta)
{
    int idx = blockIdx.x * 256 + threadIdx.x;       // < NB*C*L (exact multiple)
    int n = idx / (C * L);
    int c = (idx / L) % C;
    float mean = g_stat[n * 2], istd = g_stat[n * 2 + 1];
    out[idx] = (in[idx] - mean) * istd * gamma[c] + beta[c];
}

// ---------------- fp32 batched GEMM: 64x64 block, 4x4 per thread -----------
// C[b] = op: A [M,K] rm. TRANSB=0: B [K,N] rm ; TRANSB=1: B [N,K] rm (C=A*B^T)
// EPI=0: C = alpha*acc ; EPI=1: C = acc + R + bias[row]
template<int TRANSB, int EPI>
__global__ void __launch_bounds__(256) k_gemm(
    const float* __restrict__ A, const float* __restrict__ B, float* __restrict__ Cm,
    int M, int Nn, int K, long sA, long sB, long sC,
    float alpha, const float* __restrict__ R, long sR, const float* __restrict__ bias)
{
    __shared__ float As[16][68];
    __shared__ float Bs[16][68];
    int b = blockIdx.z;
    const float* Ab = A + (size_t)b * sA;
    const float* Bb = B + (size_t)b * sB;
    int t  = threadIdx.x;
    int tx = t & 15, ty = t >> 4;
    int rowBase = blockIdx.y * 64, colBase = blockIdx.x * 64;
    float acc[4][4] = {};
    int am = t >> 2, ak4 = (t & 3) << 2;
    int bkk = t >> 4, bn4 = (t & 15) << 2;

    for (int k0 = 0; k0 < K; k0 += 16) {
        float4 av = *(const float4*)(Ab + (size_t)(rowBase + am) * K + k0 + ak4);
        As[ak4 + 0][am] = av.x; As[ak4 + 1][am] = av.y;
        As[ak4 + 2][am] = av.z; As[ak4 + 3][am] = av.w;
        if (TRANSB) {
            float4 bv = *(const float4*)(Bb + (size_t)(colBase + am) * K + k0 + ak4);
            Bs[ak4 + 0][am] = bv.x; Bs[ak4 + 1][am] = bv.y;
            Bs[ak4 + 2][am] = bv.z; Bs[ak4 + 3][am] = bv.w;
        } else {
            float4 bv = *(const float4*)(Bb + (size_t)(k0 + bkk) * Nn + colBase + bn4);
            *(float4*)&Bs[bkk][bn4] = bv;
        }
        __syncthreads();
        #pragma unroll
        for (int kk = 0; kk < 16; kk++) {
            float4 a4 = *(float4*)&As[kk][ty << 2];
            float4 b4 = *(float4*)&Bs[kk][tx << 2];
            float ar[4] = {a4.x, a4.y, a4.z, a4.w};
            float br[4] = {b4.x, b4.y, b4.z, b4.w};
            #pragma unroll
            for (int i = 0; i < 4; i++)
                #pragma unroll
                for (int j = 0; j < 4; j++)
                    acc[i][j] += ar[i] * br[j];
        }
        __syncthreads();
    }

    float* Cb = Cm + (size_t)b * sC;
    #pragma unroll
    for (int i = 0; i < 4; i++) {
        int r  = rowBase + (ty << 2) + i;
        int cc = colBase + (tx << 2);
        float4 o;
        if (EPI == 1) {
            const float* Rb = R + (size_t)b * sR;
            float4 rv = *(const float4*)(Rb + (size_t)r * Nn + cc);
            float bv = bias[r];
            o.x = acc[i][0] + rv.x + bv; o.y = acc[i][1] + rv.y + bv;
            o.z = acc[i][2] + rv.z + bv; o.w = acc[i][3] + rv.w + bv;
        } else {
            o.x = acc[i][0] * alpha; o.y = acc[i][1] * alpha;
            o.z = acc[i][2] * alpha; o.w = acc[i][3] * alpha;
        }
        *(float4*)(Cb + (size_t)r * Nn + cc) = o;
    }
}

// ---------------- channel-attention softmax: rows of length 384 ------------
__global__ void __launch_bounds__(128) k_softmax(float* __restrict__ att) {
    float* p = att + (size_t)blockIdx.x * C;
    float v0 = p[threadIdx.x], v1 = p[threadIdx.x + 128], v2 = p[threadIdx.x + 256];
    float mx = fmaxf(v0, fmaxf(v1, v2));
    __shared__ float sh[4], sh2[4];
    #pragma unroll
    for (int o = 16; o; o >>= 1) mx = fmaxf(mx, __shfl_xor_sync(0xffffffffu, mx, o));
    if ((threadIdx.x & 31) == 0) sh[threadIdx.x >> 5] = mx;
    __syncthreads();
    mx = fmaxf(fmaxf(sh[0], sh[1]), fmaxf(sh[2], sh[3]));
    v0 = __expf(v0 - mx); v1 = __expf(v1 - mx); v2 = __expf(v2 - mx);
    float s = v0 + v1 + v2;
    #pragma unroll
    for (int o = 16; o; o >>= 1) s += __shfl_xor_sync(0xffffffffu, s, o);
    if ((threadIdx.x & 31) == 0) sh2[threadIdx.x >> 5] = s;
    __syncthreads();
    s = sh2[0] + sh2[1] + sh2[2] + sh2[3];
    float inv = 1.f / s;
    p[threadIdx.x] = v0 * inv; p[threadIdx.x + 128] = v1 * inv; p[threadIdx.x + 256] = v2 * inv;
}

// ---------------- spatial multi-head attention (fused, online softmax) -----
// one block per (n, head); thread = one query token l; K,V tiles in smem
__global__ void __launch_bounds__(256) k_spattn() {
    extern __shared__ float sh[];
    float* ks = sh;              // [HD][L]
    float* vs = sh + HD * L;     // [HD][L]
    int n = blockIdx.x / HEADS, h = blockIdx.x % HEADS;
    const float* base = g_qkv + (size_t)n * C3 * L + (size_t)h * (3 * HD) * L;
    int l = threadIdx.x;
    #pragma unroll
    for (int d = 0; d < HD; d++) {
        ks[d * L + l] = base[(HD + d) * L + l];
        vs[d * L + l] = base[(2 * HD + d) * L + l];
    }
    float q[HD];
    #pragma unroll
    for (int d = 0; d < HD; d++) q[d] = base[d * L + l];
    __syncthreads();

    float mx = -1e30f, sum = 0.f, acc[HD];
    #pragma unroll
    for (int d = 0; d < HD; d++) acc[d] = 0.f;

    for (int m = 0; m < L; m++) {
        float s = 0.f;
        #pragma unroll
        for (int d = 0; d < HD; d++) s += q[d] * ks[d * L + m];
        s *= 0.17677669529663689f;   // 1/sqrt(32)
        float nm = fmaxf(mx, s);
        float f  = __expf(mx - nm);
        float p  = __expf(s - nm);
        sum = sum * f + p;
        #pragma unroll
        for (int d = 0; d < HD; d++) acc[d] = acc[d] * f + p * vs[d * L + m];
        mx = nm;
    }
    float inv = 1.f / sum;
    float* outp = g_vals + (size_t)n * C * L + (size_t)h * HD * L + l;
    #pragma unroll
    for (int d = 0; d < HD; d++) outp[d * L] = acc[d] * inv;
}

// ---------------- depthwise convtranspose (k=8,s=4,p=2) + residual ---------
__global__ void __launch_bounds__(256) k_up(
    const float* __restrict__ x, const float* __restrict__ w,
    const float* __restrict__ ub, float* __restrict__ out)
{
    int idx = blockIdx.x * 256 + threadIdx.x;     // NB*C*64*64 exact multiple
    int xq = idx & 63;
    int yq = (idx >> 6) & 63;
    int c  = (idx >> 12) % C;
    int n  = idx / (4096 * C);
    const float* xdp = g_xd + ((size_t)n * C + c) * L;
    const float* wp  = w + c * 64;
    float acc = 0.f;
    int iy1 = (yq + 2) >> 2, ix1 = (xq + 2) >> 2;
    #pragma unroll
    for (int a = 0; a < 2; a++) {
        int iy = iy1 - a, ky = yq + 2 - 4 * iy;
        if ((unsigned)iy < 16u && (unsigned)ky < 8u) {
            #pragma unroll
            for (int b2 = 0; b2 < 2; b2++) {
                int ix = ix1 - b2, kx = xq + 2 - 4 * ix;
                if ((unsigned)ix < 16u && (unsigned)kx < 8u)
                    acc += xdp[iy * HH + ix] * wp[ky * 8 + kx];
            }
        }
    }
    out[idx] = x[idx] + acc + ub[c];
}

// ---------------- host launcher -------------------------------------------
extern "C" void kernel_launch(void* const* d_in, const int* in_sizes, int n_in,
                              void* d_out, int out_size)
{
    const float* x        = (const float*)d_in[0];
    const float* dw_w     = (const float*)d_in[1];
    const float* bn_gamma = (const float*)d_in[2];
    const float* bn_beta  = (const float*)d_in[3];
    const float* bn_mean  = (const float*)d_in[4];
    const float* bn_var   = (const float*)d_in[5];
    const float* lnch_g   = (const float*)d_in[6];
    const float* lnch_b   = (const float*)d_in[7];
    const float* pw_ch    = (const float*)d_in[8];
    const float* outch_w  = (const float*)d_in[9];
    const float* outch_b  = (const float*)d_in[10];
    const float* lnsp_g   = (const float*)d_in[11];
    const float* lnsp_b   = (const float*)d_in[12];
    const float* pw_sp    = (const float*)d_in[13];
    const float* outsp_w  = (const float*)d_in[14];
    const float* outsp_b  = (const float*)d_in[15];
    const float* up_w     = (const float*)d_in[16];
    const float* up_b     = (const float*)d_in[17];
    float* out = (float*)d_out;

    float *xd, *xd2, *gn, *qkv, *att, *vals;
    cudaGetSymbolAddress((void**)&xd,   g_xd);
    cudaGetSymbolAddress((void**)&xd2,  g_xd2);
    cudaGetSymbolAddress((void**)&gn,   g_gn);
    cudaGetSymbolAddress((void**)&qkv,  g_qkv);
    cudaGetSymbolAddress((void**)&att,  g_att);
    cudaGetSymbolAddress((void**)&vals, g_vals);

    // 1) downsample conv + BN
    k_dwconv<<<NB * C, 256>>>(x, dw_w, bn_gamma, bn_beta, bn_mean, bn_var);

    // 2-3) GroupNorm #1
    k_gnstats<<<NB, 1024>>>(xd);
    k_gnapply<<<(NB * C * L) / 256, 256>>>(xd, gn, lnch_g, lnch_b);

    // 4) qkv = pwise_ch_w @ gn   [1152 x 256] per sample
    k_gemm<0, 0><<<dim3(L / 64, C3 / 64, NB), 256>>>(
        pw_ch, gn, qkv, C3, L, C, 0, (long)C * L, (long)C3 * L,
        1.f, nullptr, 0, nullptr);

    // 5) scores = q @ k^T / 16   [384 x 384] per sample
    k_gemm<1, 0><<<dim3(C / 64, C / 64, NB), 256>>>(
        qkv, qkv + (size_t)C * L, att, C, C, L,
        (long)C3 * L, (long)C3 * L, (long)C * C,
        1.f / 16.f, nullptr, 0, nullptr);

    // 6) row softmax over d
    k_softmax<<<NB * C, 128>>>(att);

    // 7) vals = att @ v          [384 x 256]
    k_gemm<0, 0><<<dim3(L / 64, C / 64, NB), 256>>>(
        att, qkv + (size_t)2 * C * L, vals, C, L, C,
        (long)C * C, (long)C3 * L, (long)C * L,
        1.f, nullptr, 0, nullptr);

    // 8) xd2 = outch_w @ vals + xd + outch_b
    k_gemm<0, 1><<<dim3(L / 64, C / 64, NB), 256>>>(
        outch_w, vals, xd2, C, L, C, 0, (long)C * L, (long)C * L,
        1.f, xd, (long)C * L, outch_b);

    // 9-10) GroupNorm #2
    k_gnstats<<<NB, 1024>>>(xd2);
    k_gnapply<<<(NB * C * L) / 256, 256>>>(xd2, gn, lnsp_g, lnsp_b);

    // 11) qkv = pwise_sp_w @ gn
    k_gemm<0, 0><<<dim3(L / 64, C3 / 64, NB), 256>>>(
        pw_sp, gn, qkv, C3, L, C, 0, (long)C * L, (long)C3 * L,
        1.f, nullptr, 0, nullptr);

    // 12) fused spatial attention
    cudaFuncSetAttribute(k_spattn, cudaFuncAttributeMaxDynamicSharedMemorySize,
                         2 * HD * L * sizeof(float));
    k_spattn<<<NB * HEADS, 256, 2 * HD * L * sizeof(float)>>>();

    // 13) xd(final) = outsp_w @ vals + xd2 + outsp_b
    k_gemm<0, 1><<<dim3(L / 64, C / 64, NB), 256>>>(
        outsp_w, vals, xd, C, L, C, 0, (long)C * L, (long)C * L,
        1.f, xd2, (long)C * L, outsp_b);

    // 14) upsample transposed conv + residual
    k_up<<<(NB * C * HIN * HIN) / 256, 256>>>(x, up_w, up_b, out);
}

// round 2
// speedup vs baseline: 1.2796x; 1.2796x over previous
#include <cuda_runtime.h>
#include <math.h>
#include <stdint.h>

#define NB    16
#define C     384
#define C3    1152
#define HIN   64
#define HH    16
#define L     256          // HH*HH
#define HEADS 12
#define HD    32
#define EPS   1e-5f

// ---------------- scratch (device globals: allocation-free) ----------------
__device__ float g_xd  [NB * C  * L];   // x_down after conv+BN
__device__ float g_xd2 [NB * C  * L];   // after channel attention
__device__ float g_gn  [NB * C  * L];   // groupnorm output
__device__ float g_qkv [NB * C3 * L];   // qkv projections
__device__ float g_att [NB * C  * C];   // channel attention matrix
__device__ float g_vals[NB * C  * L];   // attention values
__device__ float g_stat[NB * 2];        // per-sample mean, inv_std

// ---------------- depthwise 7x7 stride-4 conv + folded BatchNorm -----------
__global__ void __launch_bounds__(256) k_dwconv(
    const float* __restrict__ x, const float* __restrict__ w,
    const float* __restrict__ bg, const float* __restrict__ bb,
    const float* __restrict__ bm, const float* __restrict__ bv)
{
    __shared__ float sx[HIN * HIN];
    __shared__ float sw[49];
    int n = blockIdx.x / C, c = blockIdx.x % C;
    const float* xp = x + ((size_t)n * C + c) * (HIN * HIN);
    for (int i = threadIdx.x; i < HIN * HIN; i += 256) sx[i] = xp[i];
    if (threadIdx.x < 49) sw[threadIdx.x] = w[c * 49 + threadIdx.x];
    __syncthreads();

    float scale = bg[c] * rsqrtf(bv[c] + EPS);
    float bias  = bb[c] - bm[c] * scale;

    int oy = threadIdx.x >> 4, ox = threadIdx.x & 15;
    int iy0 = oy * 4 - 3, ix0 = ox * 4 - 3;
    float acc = 0.f;
    #pragma unroll
    for (int ky = 0; ky < 7; ky++) {
        int iy = iy0 + ky;
        if ((unsigned)iy < (unsigned)HIN) {
            #pragma unroll
            for (int kx = 0; kx < 7; kx++) {
                int ix = ix0 + kx;
                if ((unsigned)ix < (unsigned)HIN)
                    acc += sx[iy * HIN + ix] * sw[ky * 7 + kx];
            }
        }
    }
    g_xd[((size_t)n * C + c) * L + threadIdx.x] = acc * scale + bias;
}

// ---------------- GroupNorm (1 group): per-sample stats --------------------
__device__ __forceinline__ float warpsum(float v) {
    #pragma unroll
    for (int o = 16; o; o >>= 1) v += __shfl_down_sync(0xffffffffu, v, o);
    return v;
}

__global__ void __launch_bounds__(1024) k_gnstats(const float* __restrict__ p0) {
    const float* p = p0 + (size_t)blockIdx.x * C * L;
    float s = 0.f, s2 = 0.f;
    for (int i = threadIdx.x; i < C * L; i += 1024) {
        float t = p[i]; s += t; s2 += t * t;
    }
    __shared__ float a[32], b[32];
    s = warpsum(s); s2 = warpsum(s2);
    int w = threadIdx.x >> 5, ln = threadIdx.x & 31;
    if (ln == 0) { a[w] = s; b[w] = s2; }
    __syncthreads();
    if (w == 0) {
        s = a[ln]; s2 = b[ln];
        s = warpsum(s); s2 = warpsum(s2);
        if (ln == 0) {
            float inv = 1.f / (C * L);
            float mean = s * inv;
            float var  = s2 * inv - mean * mean;
            g_stat[blockIdx.x * 2]     = mean;
            g_stat[blockIdx.x * 2 + 1] = rsqrtf(var + EPS);
        }
    }
}

__global__ void __launch_bounds__(256) k_gnapply(
    const float* __restrict__ in, float* __restrict__ out,
    const float* __restrict__ gamma, const float* __restrict__ beta)
{
    int idx = blockIdx.x * 256 + threadIdx.x;
    int n = idx / (C * L);
    int c = (idx / L) % C;
    float mean = g_stat[n * 2], istd = g_stat[n * 2 + 1];
    out[idx] = (in[idx] - mean) * istd * gamma[c] + beta[c];
}

// ---------------- tf32 helpers --------------------------------------------
__device__ __forceinline__ float to_tf32(float x) {
    uint32_t o;
    asm("cvt.rna.tf32.f32 %0, %1;" : "=r"(o) : "f"(x));
    return __uint_as_float(o);
}

__device__ __forceinline__ void mma_tf32(float c[4], const uint32_t a[4], const uint32_t b[2]) {
    asm volatile(
        "mma.sync.aligned.m16n8k8.row.col.f32.tf32.tf32.f32 "
        "{%0,%1,%2,%3}, {%4,%5,%6,%7}, {%8,%9}, {%0,%1,%2,%3};"
        : "+f"(c[0]), "+f"(c[1]), "+f"(c[2]), "+f"(c[3])
        : "r"(a[0]), "r"(a[1]), "r"(a[2]), "r"(a[3]), "r"(b[0]), "r"(b[1]));
}

// ---------------- tf32 tensor-core batched GEMM ----------------------------
// 64x64 block tile, 4 warps (2x2) each 32x32, BK=16, m16n8k8 tf32 mma.
// C[b] = op(A,B). TRANSB=0: B [K,N] rm ; TRANSB=1: B [N,K] rm (C = A*B^T)
// EPI=0: C = alpha*acc ; EPI=1: C = acc + R + bias[row]
template<int TRANSB, int EPI>
__global__ void __launch_bounds__(128) k_gemm_tc(
    const float* __restrict__ A, const float* __restrict__ B, float* __restrict__ Cm,
    int M, int Nn, int K, long sA, long sB, long sC,
    float alpha, const float* __restrict__ R, long sR, const float* __restrict__ bias)
{
    __shared__ float As[16][68];   // [k][m]
    __shared__ float Bs[16][68];   // [k][n]
    int b = blockIdx.z;
    const float* Ab = A + (size_t)b * sA;
    const float* Bb = B + (size_t)b * sB;
    int t = threadIdx.x, lane = t & 31, w = t >> 5;
    int wm = (w >> 1) * 32, wn = (w & 1) * 32;
    int rowBase = blockIdx.y * 64, colBase = blockIdx.x * 64;
    float acc[2][4][4] = {};

    int am  = t >> 2, ak4 = (t & 3) << 2;   // A/transB loader: 32 rows x 16 k per pass
    int bk  = t >> 4, bn4 = (t & 15) << 2;  // B loader: 8 k x 64 n per pass
    int lk  = lane & 3, lm = lane >> 2;

    for (int k0 = 0; k0 < K; k0 += 16) {
        #pragma unroll
        for (int r = 0; r < 2; r++) {
            int m = am + r * 32;
            float4 av = *(const float4*)(Ab + (size_t)(rowBase + m) * K + k0 + ak4);
            As[ak4 + 0][m] = to_tf32(av.x); As[ak4 + 1][m] = to_tf32(av.y);
            As[ak4 + 2][m] = to_tf32(av.z); As[ak4 + 3][m] = to_tf32(av.w);
        }
        if (TRANSB) {
            #pragma unroll
            for (int r = 0; r < 2; r++) {
                int n = am + r * 32;
                float4 bv = *(const float4*)(Bb + (size_t)(colBase + n) * K + k0 + ak4);
                Bs[ak4 + 0][n] = to_tf32(bv.x); Bs[ak4 + 1][n] = to_tf32(bv.y);
                Bs[ak4 + 2][n] = to_tf32(bv.z); Bs[ak4 + 3][n] = to_tf32(bv.w);
            }
        } else {
            #pragma unroll
            for (int r = 0; r < 2; r++) {
                int k = bk + r * 8;
                float4 bv = *(const float4*)(Bb + (size_t)(k0 + k) * Nn + colBase + bn4);
                Bs[k][bn4 + 0] = to_tf32(bv.x); Bs[k][bn4 + 1] = to_tf32(bv.y);
                Bs[k][bn4 + 2] = to_tf32(bv.z); Bs[k][bn4 + 3] = to_tf32(bv.w);
            }
        }
        __syncthreads();
        #pragma unroll
        for (int kk = 0; kk < 16; kk += 8) {
            uint32_t af[2][4], bf[4][2];
            #pragma unroll
            for (int mi = 0; mi < 2; mi++) {
                int mrow = wm + mi * 16 + lm;
                af[mi][0] = __float_as_uint(As[kk + lk    ][mrow]);
                af[mi][1] = __float_as_uint(As[kk + lk    ][mrow + 8]);
                af[mi][2] = __float_as_uint(As[kk + 4 + lk][mrow]);
                af[mi][3] = __float_as_uint(As[kk + 4 + lk][mrow + 8]);
            }
            #pragma unroll
            for (int ni = 0; ni < 4; ni++) {
                int ncol = wn + ni * 8 + lm;
                bf[ni][0] = __float_as_uint(Bs[kk + lk    ][ncol]);
                bf[ni][1] = __float_as_uint(Bs[kk + 4 + lk][ncol]);
            }
            #pragma unroll
            for (int mi = 0; mi < 2; mi++)
                #pragma unroll
                for (int ni = 0; ni < 4; ni++)
                    mma_tf32(acc[mi][ni], af[mi], bf[ni]);
        }
        __syncthreads();
    }

    float* Cb = Cm + (size_t)b * sC;
    #pragma unroll
    for (int mi = 0; mi < 2; mi++) {
        #pragma unroll
        for (int ni = 0; ni < 4; ni++) {
            int r0 = rowBase + wm + mi * 16 + lm;
            int cc = colBase + wn + ni * 8 + 2 * lk;
            if (EPI == 1) {
                const float* Rb = R + (size_t)b * sR;
                float bv0 = bias[r0], bv1 = bias[r0 + 8];
                float2 rv0 = *(const float2*)(Rb + (size_t)r0 * Nn + cc);
                float2 rv1 = *(const float2*)(Rb + (size_t)(r0 + 8) * Nn + cc);
                float2 o0 = make_float2(acc[mi][ni][0] + rv0.x + bv0,
                                        acc[mi][ni][1] + rv0.y + bv0);
                float2 o1 = make_float2(acc[mi][ni][2] + rv1.x + bv1,
                                        acc[mi][ni][3] + rv1.y + bv1);
                *(float2*)(Cb + (size_t)r0 * Nn + cc) = o0;
                *(float2*)(Cb + (size_t)(r0 + 8) * Nn + cc) = o1;
            } else {
                *(float2*)(Cb + (size_t)r0 * Nn + cc) =
                    make_float2(acc[mi][ni][0] * alpha, acc[mi][ni][1] * alpha);
                *(float2*)(Cb + (size_t)(r0 + 8) * Nn + cc) =
                    make_float2(acc[mi][ni][2] * alpha, acc[mi][ni][3] * alpha);
            }
        }
    }
}

// ---------------- channel-attention softmax: rows of length 384 ------------
__global__ void __launch_bounds__(128) k_softmax(float* __restrict__ att) {
    float* p = att + (size_t)blockIdx.x * C;
    float v0 = p[threadIdx.x], v1 = p[threadIdx.x + 128], v2 = p[threadIdx.x + 256];
    float mx = fmaxf(v0, fmaxf(v1, v2));
    __shared__ float sh[4], sh2[4];
    #pragma unroll
    for (int o = 16; o; o >>= 1) mx = fmaxf(mx, __shfl_xor_sync(0xffffffffu, mx, o));
    if ((threadIdx.x & 31) == 0) sh[threadIdx.x >> 5] = mx;
    __syncthreads();
    mx = fmaxf(fmaxf(sh[0], sh[1]), fmaxf(sh[2], sh[3]));
    v0 = __expf(v0 - mx); v1 = __expf(v1 - mx); v2 = __expf(v2 - mx);
    float s = v0 + v1 + v2;
    #pragma unroll
    for (int o = 16; o; o >>= 1) s += __shfl_xor_sync(0xffffffffu, s, o);
    if ((threadIdx.x & 31) == 0) sh2[threadIdx.x >> 5] = s;
    __syncthreads();
    s = sh2[0] + sh2[1] + sh2[2] + sh2[3];
    float inv = 1.f / s;
    p[threadIdx.x] = v0 * inv; p[threadIdx.x + 128] = v1 * inv; p[threadIdx.x + 256] = v2 * inv;
}

// ---------------- spatial multi-head attention (fused, online softmax) -----
__global__ void __launch_bounds__(256) k_spattn() {
    extern __shared__ float sh[];
    float* ks = sh;
    float* vs = sh + HD * L;
    int n = blockIdx.x / HEADS, h = blockIdx.x % HEADS;
    const float* base = g_qkv + (size_t)n * C3 * L + (size_t)h * (3 * HD) * L;
    int l = threadIdx.x;
    #pragma unroll
    for (int d = 0; d < HD; d++) {
        ks[d * L + l] = base[(HD + d) * L + l];
        vs[d * L + l] = base[(2 * HD + d) * L + l];
    }
    float q[HD];
    #pragma unroll
    for (int d = 0; d < HD; d++) q[d] = base[d * L + l];
    __syncthreads();

    float mx = -1e30f, sum = 0.f, acc[HD];
    #pragma unroll
    for (int d = 0; d < HD; d++) acc[d] = 0.f;

    for (int m = 0; m < L; m++) {
        float s = 0.f;
        #pragma unroll
        for (int d = 0; d < HD; d++) s += q[d] * ks[d * L + m];
        s *= 0.17677669529663689f;
        float nm = fmaxf(mx, s);
        float f  = __expf(mx - nm);
        float p  = __expf(s - nm);
        sum = sum * f + p;
        #pragma unroll
        for (int d = 0; d < HD; d++) acc[d] = acc[d] * f + p * vs[d * L + m];
        mx = nm;
    }
    float inv = 1.f / sum;
    float* outp = g_vals + (size_t)n * C * L + (size_t)h * HD * L + l;
    #pragma unroll
    for (int d = 0; d < HD; d++) outp[d * L] = acc[d] * inv;
}

// ---------------- depthwise convtranspose (k=8,s=4,p=2) + residual ---------
__global__ void __launch_bounds__(256) k_up(
    const float* __restrict__ x, const float* __restrict__ w,
    const float* __restrict__ ub, float* __restrict__ out)
{
    int idx = blockIdx.x * 256 + threadIdx.x;
    int xq = idx & 63;
    int yq = (idx >> 6) & 63;
    int c  = (idx >> 12) % C;
    int n  = idx / (4096 * C);
    const float* xdp = g_xd + ((size_t)n * C + c) * L;
    const float* wp  = w + c * 64;
    float acc = 0.f;
    int iy1 = (yq + 2) >> 2, ix1 = (xq + 2) >> 2;
    #pragma unroll
    for (int a = 0; a < 2; a++) {
        int iy = iy1 - a, ky = yq + 2 - 4 * iy;
        if ((unsigned)iy < 16u && (unsigned)ky < 8u) {
            #pragma unroll
            for (int b2 = 0; b2 < 2; b2++) {
                int ix = ix1 - b2, kx = xq + 2 - 4 * ix;
                if ((unsigned)ix < 16u && (unsigned)kx < 8u)
                    acc += xdp[iy * HH + ix] * wp[ky * 8 + kx];
            }
        }
    }
    out[idx] = x[idx] + acc + ub[c];
}

// ---------------- host launcher -------------------------------------------
extern "C" void kernel_launch(void* const* d_in, const int* in_sizes, int n_in,
                              void* d_out, int out_size)
{
    const float* x        = (const float*)d_in[0];
    const float* dw_w     = (const float*)d_in[1];
    const float* bn_gamma = (const float*)d_in[2];
    const float* bn_beta  = (const float*)d_in[3];
    const float* bn_mean  = (const float*)d_in[4];
    const float* bn_var   = (const float*)d_in[5];
    const float* lnch_g   = (const float*)d_in[6];
    const float* lnch_b   = (const float*)d_in[7];
    const float* pw_ch    = (const float*)d_in[8];
    const float* outch_w  = (const float*)d_in[9];
    const float* outch_b  = (const float*)d_in[10];
    const float* lnsp_g   = (const float*)d_in[11];
    const float* lnsp_b   = (const float*)d_in[12];
    const float* pw_sp    = (const float*)d_in[13];
    const float* outsp_w  = (const float*)d_in[14];
    const float* outsp_b  = (const float*)d_in[15];
    const float* up_w     = (const float*)d_in[16];
    const float* up_b     = (const float*)d_in[17];
    float* out = (float*)d_out;

    float *xd, *xd2, *gn, *qkv, *att, *vals;
    cudaGetSymbolAddress((void**)&xd,   g_xd);
    cudaGetSymbolAddress((void**)&xd2,  g_xd2);
    cudaGetSymbolAddress((void**)&gn,   g_gn);
    cudaGetSymbolAddress((void**)&qkv,  g_qkv);
    cudaGetSymbolAddress((void**)&att,  g_att);
    cudaGetSymbolAddress((void**)&vals, g_vals);

    // 1) downsample conv + BN
    k_dwconv<<<NB * C, 256>>>(x, dw_w, bn_gamma, bn_beta, bn_mean, bn_var);

    // 2-3) GroupNorm #1
    k_gnstats<<<NB, 1024>>>(xd);
    k_gnapply<<<(NB * C * L) / 256, 256>>>(xd, gn, lnch_g, lnch_b);

    // 4) qkv = pwise_ch_w @ gn   [1152 x 256] per sample
    k_gemm_tc<0, 0><<<dim3(L / 64, C3 / 64, NB), 128>>>(
        pw_ch, gn, qkv, C3, L, C, 0, (long)C * L, (long)C3 * L,
        1.f, nullptr, 0, nullptr);

    // 5) scores = q @ k^T / 16   [384 x 384] per sample
    k_gemm_tc<1, 0><<<dim3(C / 64, C / 64, NB), 128>>>(
        qkv, qkv + (size_t)C * L, att, C, C, L,
        (long)C3 * L, (long)C3 * L, (long)C * C,
        1.f / 16.f, nullptr, 0, nullptr);

    // 6) row softmax over d
    k_softmax<<<NB * C, 128>>>(att);

    // 7) vals = att @ v          [384 x 256]
    k_gemm_tc<0, 0><<<dim3(L / 64, C / 64, NB), 128>>>(
        att, qkv + (size_t)2 * C * L, vals, C, L, C,
        (long)C * C, (long)C3 * L, (long)C * L,
        1.f, nullptr, 0, nullptr);

    // 8) xd2 = outch_w @ vals + xd + outch_b
    k_gemm_tc<0, 1><<<dim3(L / 64, C / 64, NB), 128>>>(
        outch_w, vals, xd2, C, L, C, 0, (long)C * L, (long)C * L,
        1.f, xd, (long)C * L, outch_b);

    // 9-10) GroupNorm #2
    k_gnstats<<<NB, 1024>>>(xd2);
    k_gnapply<<<(NB * C * L) / 256, 256>>>(xd2, gn, lnsp_g, lnsp_b);

    // 11) qkv = pwise_sp_w @ gn
    k_gemm_tc<0, 0><<<dim3(L / 64, C3 / 64, NB), 128>>>(
        pw_sp, gn, qkv, C3, L, C, 0, (long)C * L, (long)C3 * L,
        1.f, nullptr, 0, nullptr);

    // 12) fused spatial attention
    cudaFuncSetAttribute(k_spattn, cudaFuncAttributeMaxDynamicSharedMemorySize,
                         2 * HD * L * sizeof(float));
    k_spattn<<<NB * HEADS, 256, 2 * HD * L * sizeof(float)>>>();

    // 13) xd(final) = outsp_w @ vals + xd2 + outsp_b
    k_gemm_tc<0, 1><<<dim3(L / 64, C / 64, NB), 128>>>(
        outsp_w, vals, xd, C, L, C, 0, (long)C * L, (long)C * L,
        1.f, xd2, (long)C * L, outsp_b);

    // 14) upsample transposed conv + residual
    k_up<<<(NB * C * HIN * HIN) / 256, 256>>>(x, up_w, up_b, out);
}